// round 1
// baseline (speedup 1.0000x reference)
#include <cuda_runtime.h>
#include <cuda_bf16.h>

// Problem constants
#define BB 8
#define CC 512
#define OO 512
#define HH 64
#define WW 64
#define MOD_SCALE_F 0.04419417382415922f   // 1/sqrt(512)

#define CCHUNK 8

// Scratch (device globals; no allocation in kernel_launch)
__device__ float d_s[BB * CC];           // modulation s[b,c]
__device__ float d_W2[OO * CC];          // sum_k base[o,c,k]^2
__device__ float d_g[BB * OO];           // output scale g[b,o]
__device__ float d_xs[BB * CC * HH * WW];// modulated input x*s

// ---------------------------------------------------------------------------
// Stage 1: s[b,c] = MOD_SCALE * (w[b,:] . mod_weight[c,:]) + mod_bias[c] + 1
// one warp per (b,c)
// ---------------------------------------------------------------------------
__global__ void s_kernel(const float* __restrict__ w,
                         const float* __restrict__ mw,
                         const float* __restrict__ mb) {
    int gid = blockIdx.x * blockDim.x + threadIdx.x;
    int wid = gid >> 5;
    int lane = gid & 31;
    if (wid >= BB * CC) return;
    int b = wid >> 9;
    int c = wid & 511;
    const float* wr = w + b * 512;
    const float* mr = mw + c * 512;
    float acc = 0.f;
    #pragma unroll 4
    for (int d = lane; d < 512; d += 32) acc = fmaf(wr[d], mr[d], acc);
    #pragma unroll
    for (int off = 16; off; off >>= 1) acc += __shfl_xor_sync(0xffffffffu, acc, off);
    if (lane == 0) d_s[wid] = acc * MOD_SCALE_F + mb[c] + 1.0f;
}

// ---------------------------------------------------------------------------
// Stage 2: W2[o,c] = sum_k base[o,c,k]^2
// ---------------------------------------------------------------------------
__global__ void w2_kernel(const float* __restrict__ base) {
    int i = blockIdx.x * blockDim.x + threadIdx.x;
    if (i >= OO * CC) return;
    const float* p = base + (size_t)i * 9;
    float a = 0.f;
    #pragma unroll
    for (int k = 0; k < 9; k++) { float v = p[k]; a = fmaf(v, v, a); }
    d_W2[i] = a;
}

// ---------------------------------------------------------------------------
// Stage 3: g[b,o] = rsqrt( sum_c s[b,c]^2 * W2[o,c] )   (CONV_SCALE cancels)
// one warp per (b,o)
// ---------------------------------------------------------------------------
__global__ void g_kernel() {
    int gid = blockIdx.x * blockDim.x + threadIdx.x;
    int wid = gid >> 5;
    int lane = gid & 31;
    if (wid >= BB * OO) return;
    int b = wid >> 9;
    int o = wid & 511;
    const float* sr = d_s + b * 512;
    const float* w2 = d_W2 + o * 512;
    float acc = 0.f;
    #pragma unroll 4
    for (int c = lane; c < 512; c += 32) {
        float sv = sr[c];
        acc = fmaf(sv * sv, w2[c], acc);
    }
    #pragma unroll
    for (int off = 16; off; off >>= 1) acc += __shfl_xor_sync(0xffffffffu, acc, off);
    if (lane == 0) d_g[wid] = rsqrtf(acc);
}

// ---------------------------------------------------------------------------
// Stage 4: xs[b,c,:,:] = x[b,c,:,:] * s[b,c]   (float4 vectorized)
// ---------------------------------------------------------------------------
__global__ void xs_kernel(const float* __restrict__ x) {
    int i = blockIdx.x * blockDim.x + threadIdx.x;
    if (i >= (BB * CC * HH * WW) / 4) return;
    float sc = d_s[i >> 10];  // 4096/4 = 1024 float4 per (b,c) plane
    float4 v = ((const float4*)x)[i];
    v.x *= sc; v.y *= sc; v.z *= sc; v.w *= sc;
    ((float4*)d_xs)[i] = v;
}

// ---------------------------------------------------------------------------
// Stage 5: main conv. y[b,o,h,w] = g[b,o] * conv3x3(xs[b], base)[o,h,w]
// CTA: 64 O-channels x 16x16 spatial tile, one b.
// Thread: 4 O x 4x4 pixels, 6x6 input patch cached in registers per channel.
// ---------------------------------------------------------------------------
__global__ __launch_bounds__(256, 2) void conv_kernel(
    const float* __restrict__ base, float* __restrict__ out) {
    __shared__ float sx[CCHUNK][18][20];   // padded cols for float4 alignment
    __shared__ float sw[CCHUNK][9][65];    // padded for conflict-free STS

    const int b    = blockIdx.z;
    const int og   = blockIdx.y;             // o base = og*64
    const int tile = blockIdx.x;             // 0..15
    const int th0  = (tile >> 2) << 4;
    const int tw0  = (tile & 3) << 4;
    const int tid  = threadIdx.x;
    const int tp   = tid & 15;               // pixel thread 0..15
    const int to   = tid >> 4;               // o thread 0..15
    const int pr   = (tp >> 2) << 2;         // pixel-row base 0,4,8,12
    const int pc   = (tp & 3) << 2;          // pixel-col base 0,4,8,12

    float acc[4][4][4];
    #pragma unroll
    for (int j = 0; j < 4; j++)
        #pragma unroll
        for (int r = 0; r < 4; r++)
            #pragma unroll
            for (int q = 0; q < 4; q++) acc[j][r][q] = 0.f;

    const float* xb = d_xs + (size_t)b * (CC * HH * WW);

    for (int c0 = 0; c0 < CC; c0 += CCHUNK) {
        __syncthreads();
        // load x tile (CCHUNK x 18 x 18, zero-padded halo)
        for (int idx = tid; idx < CCHUNK * 18 * 18; idx += 256) {
            int ch  = idx / 324;
            int rem = idx - ch * 324;
            int r   = rem / 18;
            int cc  = rem - r * 18;
            int gh  = th0 + r - 1;
            int gw  = tw0 + cc - 1;
            float v = 0.f;
            if (gh >= 0 && gh < HH && gw >= 0 && gw < WW)
                v = xb[((c0 + ch) * HH + gh) * WW + gw];
            sx[ch][r][cc] = v;
        }
        // load weights: 64 o x CCHUNK x 9  (base layout [o][c][k])
        for (int idx = tid; idx < 64 * CCHUNK * 9; idx += 256) {
            int oo  = idx / (CCHUNK * 9);
            int rem = idx - oo * (CCHUNK * 9);
            int cc  = rem / 9;
            int k   = rem - cc * 9;
            sw[cc][k][oo] = base[(((size_t)(og * 64 + oo)) * CC + (c0 + cc)) * 9 + k];
        }
        __syncthreads();

        for (int c = 0; c < CCHUNK; c++) {
            // cache 6x6 input patch in registers
            float xr[6][6];
            #pragma unroll
            for (int r = 0; r < 6; r++) {
                float4 v4 = *(const float4*)&sx[c][pr + r][pc];
                xr[r][0] = v4.x; xr[r][1] = v4.y; xr[r][2] = v4.z; xr[r][3] = v4.w;
                xr[r][4] = sx[c][pr + r][pc + 4];
                xr[r][5] = sx[c][pr + r][pc + 5];
            }
            #pragma unroll
            for (int ky = 0; ky < 3; ky++) {
                #pragma unroll
                for (int kx = 0; kx < 3; kx++) {
                    const int k = ky * 3 + kx;
                    float w0 = sw[c][k][to * 4 + 0];
                    float w1 = sw[c][k][to * 4 + 1];
                    float w2 = sw[c][k][to * 4 + 2];
                    float w3 = sw[c][k][to * 4 + 3];
                    #pragma unroll
                    for (int dr = 0; dr < 4; dr++) {
                        #pragma unroll
                        for (int dc = 0; dc < 4; dc++) {
                            float xv = xr[dr + ky][dc + kx];
                            acc[0][dr][dc] = fmaf(w0, xv, acc[0][dr][dc]);
                            acc[1][dr][dc] = fmaf(w1, xv, acc[1][dr][dc]);
                            acc[2][dr][dc] = fmaf(w2, xv, acc[2][dr][dc]);
                            acc[3][dr][dc] = fmaf(w3, xv, acc[3][dr][dc]);
                        }
                    }
                }
            }
        }
    }

    // epilogue: scale by g[b,o] and store (float4 rows)
    #pragma unroll
    for (int j = 0; j < 4; j++) {
        int o = og * 64 + to * 4 + j;
        float gv = d_g[b * OO + o];
        #pragma unroll
        for (int dr = 0; dr < 4; dr++) {
            int oh = th0 + pr + dr;
            float4 v;
            v.x = acc[j][dr][0] * gv;
            v.y = acc[j][dr][1] * gv;
            v.z = acc[j][dr][2] * gv;
            v.w = acc[j][dr][3] * gv;
            *(float4*)&out[(((size_t)b * OO + o) * HH + oh) * WW + tw0 + pc] = v;
        }
    }
}

// ---------------------------------------------------------------------------
extern "C" void kernel_launch(void* const* d_in, const int* in_sizes, int n_in,
                              void* d_out, int out_size) {
    // Defensive: match inputs by element count (all five are distinct).
    const float *x = nullptr, *w = nullptr, *bw = nullptr, *mw = nullptr, *mb = nullptr;
    for (int i = 0; i < n_in; i++) {
        switch (in_sizes[i]) {
            case BB * CC * HH * WW: x  = (const float*)d_in[i]; break; // 8388608
            case BB * 512:          w  = (const float*)d_in[i]; break; // 4096
            case OO * CC * 9:       bw = (const float*)d_in[i]; break; // 2359296
            case OO * CC:           mw = (const float*)d_in[i]; break; // 262144
            case CC:                mb = (const float*)d_in[i]; break; // 512
        }
    }
    float* out = (float*)d_out;

    s_kernel<<<(BB * CC * 32 + 255) / 256, 256>>>(w, mw, mb);
    w2_kernel<<<(OO * CC + 255) / 256, 256>>>(bw);
    g_kernel<<<(BB * OO * 32 + 255) / 256, 256>>>();
    xs_kernel<<<((BB * CC * HH * WW) / 4 + 255) / 256, 256>>>(x);

    dim3 grid(16, 8, 8);  // 16 spatial tiles x 8 o-groups x 8 batch
    conv_kernel<<<grid, 256>>>(bw, out);
}

// round 2
// speedup vs baseline: 1.0007x; 1.0007x over previous
#include <cuda_runtime.h>
#include <cuda_bf16.h>

// Problem constants
#define BB 8
#define CC 512
#define OO 512
#define HH 64
#define WW 64
#define MOD_SCALE_F 0.04419417382415922f   // 1/sqrt(512)

#define CCHUNK 8

// Scratch (device globals; no allocation in kernel_launch)
__device__ float d_s[BB * CC];           // modulation s[b,c]
__device__ float d_W2[OO * CC];          // sum_k base[o,c,k]^2
__device__ float d_g[BB * OO];           // output scale g[b,o]
__device__ float d_xs[BB * CC * HH * WW];// modulated input x*s

// ---------------------------------------------------------------------------
// Stage 1: s[b,c] = MOD_SCALE * (w[b,:] . mod_weight[c,:]) + mod_bias[c] + 1
// one warp per (b,c)
// ---------------------------------------------------------------------------
__global__ void s_kernel(const float* __restrict__ w,
                         const float* __restrict__ mw,
                         const float* __restrict__ mb) {
    int gid = blockIdx.x * blockDim.x + threadIdx.x;
    int wid = gid >> 5;
    int lane = gid & 31;
    if (wid >= BB * CC) return;
    int b = wid >> 9;
    int c = wid & 511;
    const float* wr = w + b * 512;
    const float* mr = mw + c * 512;
    float acc = 0.f;
    #pragma unroll 4
    for (int d = lane; d < 512; d += 32) acc = fmaf(wr[d], mr[d], acc);
    #pragma unroll
    for (int off = 16; off; off >>= 1) acc += __shfl_xor_sync(0xffffffffu, acc, off);
    if (lane == 0) d_s[wid] = acc * MOD_SCALE_F + mb[c] + 1.0f;
}

// ---------------------------------------------------------------------------
// Stage 2: W2[o,c] = sum_k base[o,c,k]^2
// ---------------------------------------------------------------------------
__global__ void w2_kernel(const float* __restrict__ base) {
    int i = blockIdx.x * blockDim.x + threadIdx.x;
    if (i >= OO * CC) return;
    const float* p = base + (size_t)i * 9;
    float a = 0.f;
    #pragma unroll
    for (int k = 0; k < 9; k++) { float v = p[k]; a = fmaf(v, v, a); }
    d_W2[i] = a;
}

// ---------------------------------------------------------------------------
// Stage 3: g[b,o] = rsqrt( sum_c s[b,c]^2 * W2[o,c] )   (CONV_SCALE cancels)
// one warp per (b,o)
// ---------------------------------------------------------------------------
__global__ void g_kernel() {
    int gid = blockIdx.x * blockDim.x + threadIdx.x;
    int wid = gid >> 5;
    int lane = gid & 31;
    if (wid >= BB * OO) return;
    int b = wid >> 9;
    int o = wid & 511;
    const float* sr = d_s + b * 512;
    const float* w2 = d_W2 + o * 512;
    float acc = 0.f;
    #pragma unroll 4
    for (int c = lane; c < 512; c += 32) {
        float sv = sr[c];
        acc = fmaf(sv * sv, w2[c], acc);
    }
    #pragma unroll
    for (int off = 16; off; off >>= 1) acc += __shfl_xor_sync(0xffffffffu, acc, off);
    if (lane == 0) d_g[wid] = rsqrtf(acc);
}

// ---------------------------------------------------------------------------
// Stage 4: xs[b,c,:,:] = x[b,c,:,:] * s[b,c]   (float4 vectorized)
// ---------------------------------------------------------------------------
__global__ void xs_kernel(const float* __restrict__ x) {
    int i = blockIdx.x * blockDim.x + threadIdx.x;
    if (i >= (BB * CC * HH * WW) / 4) return;
    float sc = d_s[i >> 10];  // 4096/4 = 1024 float4 per (b,c) plane
    float4 v = ((const float4*)x)[i];
    v.x *= sc; v.y *= sc; v.z *= sc; v.w *= sc;
    ((float4*)d_xs)[i] = v;
}

// ---------------------------------------------------------------------------
// Stage 5: main conv. y[b,o,h,w] = g[b,o] * conv3x3(xs[b], base)[o,h,w]
// CTA: 64 O-channels x 16x16 spatial tile, one b.
// Thread: 4 O x 4x4 pixels, 6x6 input patch cached in registers per channel.
// ---------------------------------------------------------------------------
__global__ __launch_bounds__(256, 2) void conv_kernel(
    const float* __restrict__ base, float* __restrict__ out) {
    __shared__ float sx[CCHUNK][18][20];   // padded cols for float4 alignment
    __shared__ float sw[CCHUNK][9][65];    // padded for conflict-free STS

    const int b    = blockIdx.z;
    const int og   = blockIdx.y;             // o base = og*64
    const int tile = blockIdx.x;             // 0..15
    const int th0  = (tile >> 2) << 4;
    const int tw0  = (tile & 3) << 4;
    const int tid  = threadIdx.x;
    const int tp   = tid & 15;               // pixel thread 0..15
    const int to   = tid >> 4;               // o thread 0..15
    const int pr   = (tp >> 2) << 2;         // pixel-row base 0,4,8,12
    const int pc   = (tp & 3) << 2;          // pixel-col base 0,4,8,12

    float acc[4][4][4];
    #pragma unroll
    for (int j = 0; j < 4; j++)
        #pragma unroll
        for (int r = 0; r < 4; r++)
            #pragma unroll
            for (int q = 0; q < 4; q++) acc[j][r][q] = 0.f;

    const float* xb = d_xs + (size_t)b * (CC * HH * WW);

    for (int c0 = 0; c0 < CC; c0 += CCHUNK) {
        __syncthreads();
        // load x tile (CCHUNK x 18 x 18, zero-padded halo)
        for (int idx = tid; idx < CCHUNK * 18 * 18; idx += 256) {
            int ch  = idx / 324;
            int rem = idx - ch * 324;
            int r   = rem / 18;
            int cc  = rem - r * 18;
            int gh  = th0 + r - 1;
            int gw  = tw0 + cc - 1;
            float v = 0.f;
            if (gh >= 0 && gh < HH && gw >= 0 && gw < WW)
                v = xb[((c0 + ch) * HH + gh) * WW + gw];
            sx[ch][r][cc] = v;
        }
        // load weights: 64 o x CCHUNK x 9  (base layout [o][c][k])
        for (int idx = tid; idx < 64 * CCHUNK * 9; idx += 256) {
            int oo  = idx / (CCHUNK * 9);
            int rem = idx - oo * (CCHUNK * 9);
            int cc  = rem / 9;
            int k   = rem - cc * 9;
            sw[cc][k][oo] = base[(((size_t)(og * 64 + oo)) * CC + (c0 + cc)) * 9 + k];
        }
        __syncthreads();

        for (int c = 0; c < CCHUNK; c++) {
            // cache 6x6 input patch in registers
            float xr[6][6];
            #pragma unroll
            for (int r = 0; r < 6; r++) {
                float4 v4 = *(const float4*)&sx[c][pr + r][pc];
                xr[r][0] = v4.x; xr[r][1] = v4.y; xr[r][2] = v4.z; xr[r][3] = v4.w;
                xr[r][4] = sx[c][pr + r][pc + 4];
                xr[r][5] = sx[c][pr + r][pc + 5];
            }
            #pragma unroll
            for (int ky = 0; ky < 3; ky++) {
                #pragma unroll
                for (int kx = 0; kx < 3; kx++) {
                    const int k = ky * 3 + kx;
                    float w0 = sw[c][k][to * 4 + 0];
                    float w1 = sw[c][k][to * 4 + 1];
                    float w2 = sw[c][k][to * 4 + 2];
                    float w3 = sw[c][k][to * 4 + 3];
                    #pragma unroll
                    for (int dr = 0; dr < 4; dr++) {
                        #pragma unroll
                        for (int dc = 0; dc < 4; dc++) {
                            float xv = xr[dr + ky][dc + kx];
                            acc[0][dr][dc] = fmaf(w0, xv, acc[0][dr][dc]);
                            acc[1][dr][dc] = fmaf(w1, xv, acc[1][dr][dc]);
                            acc[2][dr][dc] = fmaf(w2, xv, acc[2][dr][dc]);
                            acc[3][dr][dc] = fmaf(w3, xv, acc[3][dr][dc]);
                        }
                    }
                }
            }
        }
    }

    // epilogue: scale by g[b,o] and store (float4 rows)
    #pragma unroll
    for (int j = 0; j < 4; j++) {
        int o = og * 64 + to * 4 + j;
        float gv = d_g[b * OO + o];
        #pragma unroll
        for (int dr = 0; dr < 4; dr++) {
            int oh = th0 + pr + dr;
            float4 v;
            v.x = acc[j][dr][0] * gv;
            v.y = acc[j][dr][1] * gv;
            v.z = acc[j][dr][2] * gv;
            v.w = acc[j][dr][3] * gv;
            *(float4*)&out[(((size_t)b * OO + o) * HH + oh) * WW + tw0 + pc] = v;
        }
    }
}

// ---------------------------------------------------------------------------
extern "C" void kernel_launch(void* const* d_in, const int* in_sizes, int n_in,
                              void* d_out, int out_size) {
    // Defensive: match inputs by element count (all five are distinct).
    const float *x = nullptr, *w = nullptr, *bw = nullptr, *mw = nullptr, *mb = nullptr;
    for (int i = 0; i < n_in; i++) {
        switch (in_sizes[i]) {
            case BB * CC * HH * WW: x  = (const float*)d_in[i]; break; // 8388608
            case BB * 512:          w  = (const float*)d_in[i]; break; // 4096
            case OO * CC * 9:       bw = (const float*)d_in[i]; break; // 2359296
            case OO * CC:           mw = (const float*)d_in[i]; break; // 262144
            case CC:                mb = (const float*)d_in[i]; break; // 512
        }
    }
    float* out = (float*)d_out;

    s_kernel<<<(BB * CC * 32 + 255) / 256, 256>>>(w, mw, mb);
    w2_kernel<<<(OO * CC + 255) / 256, 256>>>(bw);
    g_kernel<<<(BB * OO * 32 + 255) / 256, 256>>>();
    xs_kernel<<<((BB * CC * HH * WW) / 4 + 255) / 256, 256>>>(x);

    dim3 grid(16, 8, 8);  // 16 spatial tiles x 8 o-groups x 8 batch
    conv_kernel<<<grid, 256>>>(bw, out);
}